// round 8
// baseline (speedup 1.0000x reference)
#include <cuda_runtime.h>
#include <cuda_bf16.h>
#include <cstdint>
#include <math.h>

#define BSZ 4096
#define FDIM 768
#define PDIM 500
#define ZDIM 300
#define RNUM 10
#define NRET (BSZ * RNUM)          // 40960
#define EDGE_ROWS (BSZ * 4)        // 16384
#define M_ROWS (EDGE_ROWS + RNUM)  // 16394
#define FEATD 2100
#define H1D 800
#define H2D 200

// ---------------- scratch (device globals) ----------------
__device__ float g_Rout[3ull * NRET * PDIM];
__device__ float g_E[3ull * BSZ * PDIM];
__device__ float g_M[(size_t)M_ROWS * PDIM];
__device__ float g_Y[(size_t)M_ROWS * ZDIM];
__device__ float g_feat[(size_t)BSZ * FEATD];
__device__ float g_h1[(size_t)BSZ * H1D];
__device__ float g_h2[(size_t)BSZ * H2D];

// ---------------- warp-MMA helpers ----------------
__device__ __forceinline__ uint32_t smem_u32(const void* p) {
    uint32_t a;
    asm("{ .reg .u64 t; cvta.to.shared.u64 t, %1; cvt.u32.u64 %0, t; }" : "=r"(a) : "l"(p));
    return a;
}
__device__ __forceinline__ void ldsm4(uint32_t* r, uint32_t addr) {
    asm volatile("ldmatrix.sync.aligned.m8n8.x4.shared.b16 {%0,%1,%2,%3}, [%4];"
                 : "=r"(r[0]), "=r"(r[1]), "=r"(r[2]), "=r"(r[3]) : "r"(addr));
}
__device__ __forceinline__ void mma16816(float* d, const uint32_t* a, uint32_t b0, uint32_t b1) {
    asm volatile(
        "mma.sync.aligned.m16n8k16.row.col.f32.bf16.bf16.f32 "
        "{%0,%1,%2,%3}, {%4,%5,%6,%7}, {%8,%9}, {%0,%1,%2,%3};"
        : "+f"(d[0]), "+f"(d[1]), "+f"(d[2]), "+f"(d[3])
        : "r"(a[0]), "r"(a[1]), "r"(a[2]), "r"(a[3]), "r"(b0), "r"(b1));
}
__device__ __forceinline__ uint32_t packbf(__nv_bfloat16 x, __nv_bfloat16 y) {
    __nv_bfloat162 t; t.x = x; t.y = y;
    return *reinterpret_cast<uint32_t*>(&t);
}
// 16B-chunk XOR swizzle for 64B rows
__device__ __forceinline__ uint32_t swz(int row, int chunk) {
    return (uint32_t)(row * 64 + ((chunk ^ ((row >> 1) & 3)) << 4));
}

#define STAGE_BYTES 32768  // Ahi 8K | Alo 8K | Whi 8K | Wlo 8K
#define SMEM_BYTES 65536

struct GemmArgs { const float *A, *W, *bias; float *C; };
struct GemmBatch { GemmArgs g[3]; };

// ============ split-bf16 HMMA GEMM: C = epi(A[M,K] @ W[N,K]^T + bias) ============
// 512 thr / 16 warps, block 128x128, warp 32x32, double-buffered, pass-major MMA order.
// 3-pass: D = Ahi*Whi + Alo*Whi + Ahi*Wlo
template <int EPI>  // 0=none, 1=tanh, 2=relu
__global__ void __launch_bounds__(512, 1)
hgemm(GemmBatch batch, int M, int N, int K) {
    const GemmArgs ga = batch.g[blockIdx.z];
    const float* __restrict__ A = ga.A;
    const float* __restrict__ W = ga.W;
    const float* __restrict__ bias = ga.bias;
    float* __restrict__ C = ga.C;

    extern __shared__ char smem[];
    const uint32_t sbase = smem_u32(smem);
    const int tid = threadIdx.x, wid = tid >> 5, lane = tid & 31;
    const int bm = blockIdx.y * 128, bn = blockIdx.x * 128;
    const int wm = (wid & 3) * 32;
    const int wn = (wid >> 2) * 32;

    float acc[8][4];
#pragma unroll
    for (int i = 0; i < 8; i++)
#pragma unroll
        for (int j = 0; j < 4; j++) acc[i][j] = 0.f;

    const int nch = (K + 31) >> 5;
    float4 pa[2], pw[2];

    auto loadg = [&](int c) {
        const int kk0 = c << 5;
#pragma unroll
        for (int i = 0; i < 2; i++) {
            const int slot = tid + (i << 9);
            const int row = slot >> 3, c4 = slot & 7;
            const int gk = kk0 + (c4 << 2);
            const int gm = bm + row;
            float4 v = make_float4(0.f, 0.f, 0.f, 0.f);
            if (gm < M) {
                if (gk + 4 <= K) v = *reinterpret_cast<const float4*>(A + (size_t)gm * K + gk);
                else {
                    float t[4] = {0.f, 0.f, 0.f, 0.f};
                    for (int q = 0; q < 4; q++) if (gk + q < K) t[q] = A[(size_t)gm * K + gk + q];
                    v = make_float4(t[0], t[1], t[2], t[3]);
                }
            }
            pa[i] = v;
            const int gn = bn + row;
            float4 w = make_float4(0.f, 0.f, 0.f, 0.f);
            if (gn < N) {
                if (gk + 4 <= K) w = *reinterpret_cast<const float4*>(W + (size_t)gn * K + gk);
                else {
                    float t[4] = {0.f, 0.f, 0.f, 0.f};
                    for (int q = 0; q < 4; q++) if (gk + q < K) t[q] = W[(size_t)gn * K + gk + q];
                    w = make_float4(t[0], t[1], t[2], t[3]);
                }
            }
            pw[i] = w;
        }
    };

    auto stores = [&](int st) {
        char* base = smem + st * STAGE_BYTES;
#pragma unroll
        for (int i = 0; i < 2; i++) {
            const int slot = tid + (i << 9);
            const int row = slot >> 3, c4 = slot & 7;
            const uint32_t byte = swz(row, c4 >> 1) + ((c4 & 1) << 3);
#pragma unroll
            for (int half = 0; half < 2; half++) {
                const float4 v = half ? pw[i] : pa[i];
                const __nv_bfloat16 h0 = __float2bfloat16(v.x), h1 = __float2bfloat16(v.y);
                const __nv_bfloat16 h2 = __float2bfloat16(v.z), h3 = __float2bfloat16(v.w);
                const __nv_bfloat16 l0 = __float2bfloat16(v.x - __bfloat162float(h0));
                const __nv_bfloat16 l1 = __float2bfloat16(v.y - __bfloat162float(h1));
                const __nv_bfloat16 l2 = __float2bfloat16(v.z - __bfloat162float(h2));
                const __nv_bfloat16 l3 = __float2bfloat16(v.w - __bfloat162float(h3));
                uint2 hi, lo;
                hi.x = packbf(h0, h1); hi.y = packbf(h2, h3);
                lo.x = packbf(l0, l1); lo.y = packbf(l2, l3);
                char* r = base + half * 16384;
                *reinterpret_cast<uint2*>(r + byte) = hi;
                *reinterpret_cast<uint2*>(r + 8192 + byte) = lo;
            }
        }
    };

    // pass-major MMA: same-accumulator reuse distance = 8 independent MMAs
    auto do_mma = [&](int st) {
        const uint32_t sA = sbase + st * STAGE_BYTES;
        const uint32_t sW = sA + 16384;
#pragma unroll
        for (int ks = 0; ks < 2; ks++) {
            uint32_t ah[2][4], al[2][4], wh[2][4], wl[2][4];
#pragma unroll
            for (int mi = 0; mi < 2; mi++) {
                const int r = wm + mi * 16 + (lane & 15);
                const int c = 2 * ks + (lane >> 4);
                const uint32_t byte = swz(r, c);
                ldsm4(ah[mi], sA + byte);
                ldsm4(al[mi], sA + 8192 + byte);
            }
#pragma unroll
            for (int ng = 0; ng < 2; ng++) {
                const int r = wn + ng * 16 + ((lane >> 4) << 3) + (lane & 7);
                const int c = 2 * ks + ((lane >> 3) & 1);
                const uint32_t byte = swz(r, c);
                ldsm4(wh[ng], sW + byte);
                ldsm4(wl[ng], sW + 8192 + byte);
            }
            // pass 1: Ahi * Whi
#pragma unroll
            for (int mi = 0; mi < 2; mi++)
#pragma unroll
                for (int ng = 0; ng < 2; ng++)
#pragma unroll
                    for (int sub = 0; sub < 2; sub++)
                        mma16816(acc[mi * 4 + ng * 2 + sub], ah[mi], wh[ng][2 * sub], wh[ng][2 * sub + 1]);
            // pass 2: Alo * Whi
#pragma unroll
            for (int mi = 0; mi < 2; mi++)
#pragma unroll
                for (int ng = 0; ng < 2; ng++)
#pragma unroll
                    for (int sub = 0; sub < 2; sub++)
                        mma16816(acc[mi * 4 + ng * 2 + sub], al[mi], wh[ng][2 * sub], wh[ng][2 * sub + 1]);
            // pass 3: Ahi * Wlo
#pragma unroll
            for (int mi = 0; mi < 2; mi++)
#pragma unroll
                for (int ng = 0; ng < 2; ng++)
#pragma unroll
                    for (int sub = 0; sub < 2; sub++)
                        mma16816(acc[mi * 4 + ng * 2 + sub], ah[mi], wl[ng][2 * sub], wl[ng][2 * sub + 1]);
        }
    };

    loadg(0);
    stores(0);
    __syncthreads();
    for (int c = 0; c < nch; c++) {
        if (c + 1 < nch) loadg(c + 1);
        do_mma(c & 1);
        if (c + 1 < nch) stores((c + 1) & 1);
        __syncthreads();
    }

    // ---- epilogue ----
#pragma unroll
    for (int mi = 0; mi < 2; mi++)
#pragma unroll
        for (int nj = 0; nj < 4; nj++) {
            const float* d = acc[mi * 4 + nj];
            const int gm = bm + wm + mi * 16 + (lane >> 2);
            const int gn = bn + wn + nj * 8 + (lane & 3) * 2;
            if (gn < N) {
                const float b0 = __ldg(bias + gn), b1 = __ldg(bias + gn + 1);
                if (gm < M) {
                    float2 o;
                    o.x = d[0] + b0; o.y = d[1] + b1;
                    if (EPI == 1) { o.x = tanhf(o.x); o.y = tanhf(o.y); }
                    else if (EPI == 2) { o.x = fmaxf(o.x, 0.f); o.y = fmaxf(o.y, 0.f); }
                    *reinterpret_cast<float2*>(C + (size_t)gm * N + gn) = o;
                }
                if (gm + 8 < M) {
                    float2 o;
                    o.x = d[2] + b0; o.y = d[3] + b1;
                    if (EPI == 1) { o.x = tanhf(o.x); o.y = tanhf(o.y); }
                    else if (EPI == 2) { o.x = fmaxf(o.x, 0.f); o.y = fmaxf(o.y, 0.f); }
                    *reinterpret_cast<float2*>(C + (size_t)(gm + 8) * N + gn) = o;
                }
            }
        }
}

// ---------------- fused retrieved-sum + edge-mean kernel ----------------
__global__ void build_means_fused() {
    const int idx = blockIdx.x * blockDim.x + threadIdx.x;
    if (idx >= BSZ * (PDIM / 4)) return;
    const int b = idx / (PDIM / 4), p4 = (idx % (PDIM / 4)) * 4;

    const float4 et = *reinterpret_cast<const float4*>(g_E + ((size_t)0 * BSZ + b) * PDIM + p4);
    const float4 ev = *reinterpret_cast<const float4*>(g_E + ((size_t)1 * BSZ + b) * PDIM + p4);
    const float4 eu = *reinterpret_cast<const float4*>(g_E + ((size_t)2 * BSZ + b) * PDIM + p4);

    float4 S[3];
#pragma unroll
    for (int s = 0; s < 3; s++) {
        const float* base = g_Rout + (size_t)s * NRET * PDIM + (size_t)b * RNUM * PDIM + p4;
        float4 acc = make_float4(0.f, 0.f, 0.f, 0.f);
#pragma unroll
        for (int i = 0; i < RNUM; i++) {
            const float4 v = *reinterpret_cast<const float4*>(base + (size_t)i * PDIM);
            acc.x += v.x; acc.y += v.y; acc.z += v.z; acc.w += v.w;
        }
        S[s] = acc;
    }
    float* row = g_M + (size_t)b * 4 * PDIM + p4;
    const float i3 = 1.f / 3.f, i11 = 1.f / 11.f;
    float4 o0, o1, o2, o3;
    o0.x = (et.x + ev.x + eu.x) * i3; o0.y = (et.y + ev.y + eu.y) * i3;
    o0.z = (et.z + ev.z + eu.z) * i3; o0.w = (et.w + ev.w + eu.w) * i3;
    o1.x = (S[0].x + et.x) * i11; o1.y = (S[0].y + et.y) * i11;
    o1.z = (S[0].z + et.z) * i11; o1.w = (S[0].w + et.w) * i11;
    o2.x = (S[1].x + ev.x) * i11; o2.y = (S[1].y + ev.y) * i11;
    o2.z = (S[1].z + ev.z) * i11; o2.w = (S[1].w + ev.w) * i11;
    o3.x = (S[2].x + eu.x) * i11; o3.y = (S[2].y + eu.y) * i11;
    o3.z = (S[2].z + eu.z) * i11; o3.w = (S[2].w + eu.w) * i11;
    *reinterpret_cast<float4*>(row + 0 * PDIM) = o0;
    *reinterpret_cast<float4*>(row + 1 * PDIM) = o1;
    *reinterpret_cast<float4*>(row + 2 * PDIM) = o2;
    *reinterpret_cast<float4*>(row + 3 * PDIM) = o3;
}

__global__ void build_pair_means() {
    const int idx = blockIdx.x * blockDim.x + threadIdx.x;
    if (idx >= RNUM * PDIM) return;
    const int i = idx / PDIM, p = idx % PDIM;
    const float a = g_Rout[(size_t)0 * NRET * PDIM + (size_t)i * PDIM + p];
    const float c = g_Rout[(size_t)1 * NRET * PDIM + (size_t)i * PDIM + p];
    g_M[(size_t)(EDGE_ROWS + i) * PDIM + p] = 0.5f * (a + c);
}

__global__ void build_feat(const float* __restrict__ similarity,
                           const float* __restrict__ rlabel,
                           const float* __restrict__ lbl_w,
                           const float* __restrict__ lbl_b) {
    const int b = blockIdx.x;
    __shared__ float ssim[RNUM];
    __shared__ float s_lbl;
    if (threadIdx.x == 0) {
        float v[RNUM], mx = -1e30f;
#pragma unroll
        for (int i = 0; i < RNUM; i++) { v[i] = similarity[b * RNUM + i]; mx = fmaxf(mx, v[i]); }
        float sum = 0.f;
#pragma unroll
        for (int i = 0; i < RNUM; i++) { v[i] = expf(v[i] - mx); sum += v[i]; }
        float la = 0.f;
        const float inv = 1.f / sum;
#pragma unroll
        for (int i = 0; i < RNUM; i++) {
            v[i] *= inv; ssim[i] = v[i];
            la += v[i] * rlabel[b * RNUM + i];
        }
        s_lbl = la;
    }
    __syncthreads();
    const float* Yb = g_Y + (size_t)b * 4 * ZDIM;
    float* fb = g_feat + (size_t)b * FEATD;
    const float lagg = s_lbl;
    for (int z = threadIdx.x; z < ZDIM; z += blockDim.x) {
        const float Y0 = Yb[z], Y1 = Yb[ZDIM + z], Y2 = Yb[2 * ZDIM + z], Y3 = Yb[3 * ZDIM + z];
        fb[z]            = fmaxf(0.5f * (Y0 + Y1), 0.f);
        fb[ZDIM + z]     = fmaxf(0.5f * (Y0 + Y2), 0.f);
        fb[2 * ZDIM + z] = fmaxf(0.5f * (Y0 + Y3), 0.f);
        float rv, rt;
        if (b != 0) {
            rv = fmaxf(Y2, 0.f);
            rt = fmaxf(Y1, 0.f);
        } else {
            rv = 0.f; rt = 0.f;
#pragma unroll
            for (int i = 0; i < RNUM; i++) {
                const float yp = g_Y[(size_t)(EDGE_ROWS + i) * ZDIM + z];
                rt += ssim[i] * fmaxf(0.5f * (Y1 + yp), 0.f);
                rv += ssim[i] * fmaxf(0.5f * (Y2 + yp), 0.f);
            }
        }
        fb[3 * ZDIM + z] = rv;
        fb[4 * ZDIM + z] = rt;
        fb[5 * ZDIM + z] = fmaxf(Y3, 0.f);
        fb[6 * ZDIM + z] = fmaxf(lagg * lbl_w[z] + lbl_b[z], 0.f);
    }
}

__global__ void final_out(const float* __restrict__ p3_w, const float* __restrict__ p3_b,
                          float* __restrict__ out) {
    const int warp = (blockIdx.x * blockDim.x + threadIdx.x) >> 5;
    const int lane = threadIdx.x & 31;
    if (warp >= BSZ) return;
    const float* h = g_h2 + (size_t)warp * H2D;
    float s = 0.f;
    for (int j = lane; j < H2D; j += 32) s += h[j] * p3_w[j];
#pragma unroll
    for (int off = 16; off; off >>= 1) s += __shfl_xor_sync(0xffffffffu, s, off);
    if (lane == 0) out[warp] = 1.f / (1.f + expf(-(s + p3_b[0])));
}

// ---------------- host launcher ----------------
extern "C" void kernel_launch(void* const* d_in, const int* in_sizes, int n_in,
                              void* d_out, int out_size) {
    const float* vis   = (const float*)d_in[0];
    const float* txt   = (const float*)d_in[1];
    const float* sim   = (const float*)d_in[2];
    const float* rvis  = (const float*)d_in[3];
    const float* rtxt  = (const float*)d_in[4];
    const float* rlbl  = (const float*)d_in[5];
    const float* usr   = (const float*)d_in[6];
    const float* rusr  = (const float*)d_in[7];
    const float* vis_w = (const float*)d_in[9],  *vis_b = (const float*)d_in[10];
    const float* txt_w = (const float*)d_in[11], *txt_b = (const float*)d_in[12];
    const float* usr_w = (const float*)d_in[13], *usr_b = (const float*)d_in[14];
    const float* rvis_w = (const float*)d_in[15], *rvis_b = (const float*)d_in[16];
    const float* rtxt_w = (const float*)d_in[17], *rtxt_b = (const float*)d_in[18];
    const float* rusr_w = (const float*)d_in[19], *rusr_b = (const float*)d_in[20];
    const float* hg_w  = (const float*)d_in[21], *hg_b = (const float*)d_in[22];
    const float* lbl_w = (const float*)d_in[23], *lbl_b = (const float*)d_in[24];
    const float* p1_w  = (const float*)d_in[25], *p1_b = (const float*)d_in[26];
    const float* p2_w  = (const float*)d_in[27], *p2_b = (const float*)d_in[28];
    const float* p3_w  = (const float*)d_in[29], *p3_b = (const float*)d_in[30];

    float *Rout, *E, *Mb, *Y, *feat, *h1, *h2;
    cudaGetSymbolAddress((void**)&Rout, g_Rout);
    cudaGetSymbolAddress((void**)&E, g_E);
    cudaGetSymbolAddress((void**)&Mb, g_M);
    cudaGetSymbolAddress((void**)&Y, g_Y);
    cudaGetSymbolAddress((void**)&feat, g_feat);
    cudaGetSymbolAddress((void**)&h1, g_h1);
    cudaGetSymbolAddress((void**)&h2, g_h2);

    cudaFuncSetAttribute(hgemm<0>, cudaFuncAttributeMaxDynamicSharedMemorySize, SMEM_BYTES);
    cudaFuncSetAttribute(hgemm<1>, cudaFuncAttributeMaxDynamicSharedMemorySize, SMEM_BYTES);
    cudaFuncSetAttribute(hgemm<2>, cudaFuncAttributeMaxDynamicSharedMemorySize, SMEM_BYTES);

    const dim3 blk(512);

    // 1a) three single-sample embeds, batched over blockIdx.z
    {
        GemmBatch gb;
        gb.g[0] = {txt, txt_w, txt_b, E + (size_t)0 * BSZ * PDIM};
        gb.g[1] = {vis, vis_w, vis_b, E + (size_t)1 * BSZ * PDIM};
        gb.g[2] = {usr, usr_w, usr_b, E + (size_t)2 * BSZ * PDIM};
        hgemm<1><<<dim3((PDIM + 127) / 128, (BSZ + 127) / 128, 3), blk, SMEM_BYTES>>>(gb, BSZ, PDIM, FDIM);
    }
    // 1b) three retrieved embeds, batched
    {
        GemmBatch gb;
        gb.g[0] = {rtxt, rtxt_w, rtxt_b, Rout + (size_t)0 * NRET * PDIM};
        gb.g[1] = {rvis, rvis_w, rvis_b, Rout + (size_t)1 * NRET * PDIM};
        gb.g[2] = {rusr, rusr_w, rusr_b, Rout + (size_t)2 * NRET * PDIM};
        hgemm<1><<<dim3((PDIM + 127) / 128, (NRET + 127) / 128, 3), blk, SMEM_BYTES>>>(gb, NRET, PDIM, FDIM);
    }

    // 2+3) fused retrieved sums + edge means
    build_means_fused<<<(BSZ * (PDIM / 4) + 255) / 256, 256>>>();
    build_pair_means<<<(RNUM * PDIM + 255) / 256, 256>>>();

    // 4) hypergraph projection
    {
        GemmBatch gb; gb.g[0] = {Mb, hg_w, hg_b, Y}; gb.g[1] = gb.g[0]; gb.g[2] = gb.g[0];
        hgemm<0><<<dim3((ZDIM + 127) / 128, (M_ROWS + 127) / 128, 1), blk, SMEM_BYTES>>>(gb, M_ROWS, ZDIM, PDIM);
    }

    // 5) feature assembly
    build_feat<<<BSZ, 256>>>(sim, rlbl, lbl_w, lbl_b);

    // 6) MLP head
    {
        GemmBatch gb; gb.g[0] = {feat, p1_w, p1_b, h1}; gb.g[1] = gb.g[0]; gb.g[2] = gb.g[0];
        hgemm<2><<<dim3((H1D + 127) / 128, (BSZ + 127) / 128, 1), blk, SMEM_BYTES>>>(gb, BSZ, H1D, FEATD);
    }
    {
        GemmBatch gb; gb.g[0] = {h1, p2_w, p2_b, h2}; gb.g[1] = gb.g[0]; gb.g[2] = gb.g[0];
        hgemm<2><<<dim3((H2D + 127) / 128, (BSZ + 127) / 128, 1), blk, SMEM_BYTES>>>(gb, BSZ, H2D, H1D);
    }
    final_out<<<(BSZ * 32 + 255) / 256, 256>>>(p3_w, p3_b, (float*)d_out);
}

// round 9
// speedup vs baseline: 1.0922x; 1.0922x over previous
#include <cuda_runtime.h>
#include <cuda_bf16.h>
#include <cstdint>
#include <math.h>

#define BSZ 4096
#define FDIM 768
#define PDIM 500
#define ZDIM 300
#define RNUM 10
#define NRET (BSZ * RNUM)          // 40960
#define EDGE_ROWS (BSZ * 4)        // 16384
#define M_ROWS (EDGE_ROWS + RNUM)  // 16394
#define FEATD 2100
#define H1D 800
#define H2D 200

// padded plane dims
#define MROWS_P 16512              // 129*128
#define KP_HG 512
#define KP_P1 2112
#define KP_P2 800

// ---------------- fp32 scratch ----------------
__device__ float g_Rout[3ull * NRET * PDIM];
__device__ float g_E[3ull * BSZ * PDIM];
__device__ float g_Y[(size_t)M_ROWS * ZDIM];
__device__ float g_h2[(size_t)BSZ * H2D];
__device__ float g_bias[8192];
// bias layout: [0..6*512) embeds, [3072..3584) hg, [3584..4608) p1, [4608..4864) p2

// ---------------- bf16 hi/lo planes (hi first, then lo) ----------------
__device__ __align__(16) __nv_bfloat16 g_aS[3ull * 2 * BSZ * FDIM];      // singles A
__device__ __align__(16) __nv_bfloat16 g_aR[3ull * 2 * NRET * FDIM];     // retrieved A
__device__ __align__(16) __nv_bfloat16 g_wE[6ull * 2 * 512 * FDIM];      // 6 embed weights (500->512 rows)
__device__ __align__(16) __nv_bfloat16 g_aM[2ull * MROWS_P * KP_HG];     // hg A (edge means)
__device__ __align__(16) __nv_bfloat16 g_wHg[2ull * 512 * KP_HG];        // hg W (300->512 rows)
__device__ __align__(16) __nv_bfloat16 g_aF[2ull * BSZ * KP_P1];         // feat A
__device__ __align__(16) __nv_bfloat16 g_wP1[2ull * 1024 * KP_P1];       // p1 W (800->1024)
__device__ __align__(16) __nv_bfloat16 g_aH1[2ull * BSZ * KP_P2];        // h1 A
__device__ __align__(16) __nv_bfloat16 g_wP2[2ull * 256 * KP_P2];        // p2 W (200->256)

// ---------------- helpers ----------------
__device__ __forceinline__ uint32_t smem_u32(const void* p) {
    uint32_t a;
    asm("{ .reg .u64 t; cvta.to.shared.u64 t, %1; cvt.u32.u64 %0, t; }" : "=r"(a) : "l"(p));
    return a;
}
__device__ __forceinline__ void ldsm4(uint32_t* r, uint32_t addr) {
    asm volatile("ldmatrix.sync.aligned.m8n8.x4.shared.b16 {%0,%1,%2,%3}, [%4];"
                 : "=r"(r[0]), "=r"(r[1]), "=r"(r[2]), "=r"(r[3]) : "r"(addr));
}
__device__ __forceinline__ void mma16816(float* d, const uint32_t* a, uint32_t b0, uint32_t b1) {
    asm volatile(
        "mma.sync.aligned.m16n8k16.row.col.f32.bf16.bf16.f32 "
        "{%0,%1,%2,%3}, {%4,%5,%6,%7}, {%8,%9}, {%0,%1,%2,%3};"
        : "+f"(d[0]), "+f"(d[1]), "+f"(d[2]), "+f"(d[3])
        : "r"(a[0]), "r"(a[1]), "r"(a[2]), "r"(a[3]), "r"(b0), "r"(b1));
}
__device__ __forceinline__ uint32_t swz(int row, int chunk) {
    return (uint32_t)(row * 64 + ((chunk ^ ((row >> 1) & 3)) << 4));
}
__device__ __forceinline__ void cpa16(uint32_t dst, const void* src) {
    asm volatile("cp.async.cg.shared.global [%0], [%1], 16;" :: "r"(dst), "l"(src));
}
__device__ __forceinline__ void cpa_commit() {
    asm volatile("cp.async.commit_group;" ::: "memory");
}
__device__ __forceinline__ void store_hl(__nv_bfloat16* hi, __nv_bfloat16* lo, float v) {
    const __nv_bfloat16 h = __float2bfloat16(v);
    *hi = h;
    *lo = __float2bfloat16(v - __bfloat162float(h));
}

#define STAGE_B 49152                 // Ahi8K Alo8K Whi16K Wlo16K
#define SMEM_BYTES (4 * STAGE_B)      // 196608

// ============ split-bf16 HMMA GEMM on preconverted planes ============
// block 128x256, 8 warps (warp 64x64), 4-stage cp.async, 3-pass split.
template <int EPI, int OUT>  // EPI: 0 none,1 tanh,2 relu ; OUT: 0 fp32, 1 hi/lo plane
__global__ void __launch_bounds__(256, 1)
hgemm(const __nv_bfloat16* __restrict__ Ap, size_t aZ, size_t aLo,
      const __nv_bfloat16* __restrict__ Wp, size_t wZ, size_t wLo,
      const float* __restrict__ bias, int bStride,
      void* __restrict__ Cp, size_t cZ, size_t cLo, int ldC,
      int M, int N, int Kp) {
    extern __shared__ char smem[];
    const uint32_t sb = smem_u32(smem);
    const int tid = threadIdx.x, wid = tid >> 5, lane = tid & 31;
    const int bm = blockIdx.y * 128, bn = blockIdx.x * 256;
    const int z = blockIdx.z;
    const __nv_bfloat16* Ab = Ap + (size_t)z * aZ;
    const __nv_bfloat16* Wb = Wp + (size_t)z * wZ;
    const float* bb = bias + (size_t)z * bStride;
    const int wm = (wid & 1) * 64, wn = (wid >> 1) * 64;
    const int nch = Kp >> 5;

    float acc[32][4];
#pragma unroll
    for (int i = 0; i < 32; i++)
#pragma unroll
        for (int j = 0; j < 4; j++) acc[i][j] = 0.f;

    auto fill = [&](int c) {
        if (c >= nch) return;
        const int k0 = c << 5;
        const uint32_t st = sb + (uint32_t)(c & 3) * STAGE_B;
#pragma unroll
        for (int i = 0; i < 2; i++) {  // A: 512 granules/half
            const int g = tid + (i << 8);
            const int row = g >> 2, ch = g & 3;
            const uint32_t so = swz(row, ch);
            const size_t off = (size_t)(bm + row) * Kp + k0 + ch * 8;
            cpa16(st + so, Ab + off);
            cpa16(st + 8192 + so, Ab + aLo + off);
        }
#pragma unroll
        for (int i = 0; i < 4; i++) {  // W: 1024 granules/half
            const int g = tid + (i << 8);
            const int row = g >> 2, ch = g & 3;
            const uint32_t so = swz(row, ch);
            const size_t off = (size_t)(bn + row) * Kp + k0 + ch * 8;
            cpa16(st + 16384 + so, Wb + off);
            cpa16(st + 32768 + so, Wb + wLo + off);
        }
    };

    fill(0); cpa_commit();
    fill(1); cpa_commit();
    fill(2); cpa_commit();

    for (int c = 0; c < nch; c++) {
        asm volatile("cp.async.wait_group 2;" ::: "memory");
        __syncthreads();
        fill(c + 3);
        cpa_commit();

        const uint32_t st = sb + (uint32_t)(c & 3) * STAGE_B;
        const uint32_t sAh = st, sAl = st + 8192, sWh = st + 16384, sWl = st + 32768;
#pragma unroll
        for (int ks = 0; ks < 2; ks++) {
            uint32_t ah[4][4], al[4][4];
#pragma unroll
            for (int mi = 0; mi < 4; mi++) {
                const int r = wm + mi * 16 + (lane & 15);
                const int cc = 2 * ks + (lane >> 4);
                const uint32_t so = swz(r, cc);
                ldsm4(ah[mi], sAh + so);
                ldsm4(al[mi], sAl + so);
            }
#pragma unroll
            for (int ng = 0; ng < 4; ng++) {
                const int r = wn + ng * 16 + ((lane >> 4) << 3) + (lane & 7);
                const int cc = 2 * ks + ((lane >> 3) & 1);
                const uint32_t so = swz(r, cc);
                uint32_t wh[4], wl[4];
                ldsm4(wh, sWh + so);
                ldsm4(wl, sWl + so);
                // pass 1: Ahi*Whi (8 independent MMAs)
#pragma unroll
                for (int mi = 0; mi < 4; mi++)
#pragma unroll
                    for (int sub = 0; sub < 2; sub++)
                        mma16816(acc[mi * 8 + ng * 2 + sub], ah[mi], wh[2 * sub], wh[2 * sub + 1]);
                // pass 2: Alo*Whi
#pragma unroll
                for (int mi = 0; mi < 4; mi++)
#pragma unroll
                    for (int sub = 0; sub < 2; sub++)
                        mma16816(acc[mi * 8 + ng * 2 + sub], al[mi], wh[2 * sub], wh[2 * sub + 1]);
                // pass 3: Ahi*Wlo
#pragma unroll
                for (int mi = 0; mi < 4; mi++)
#pragma unroll
                    for (int sub = 0; sub < 2; sub++)
                        mma16816(acc[mi * 8 + ng * 2 + sub], ah[mi], wl[2 * sub], wl[2 * sub + 1]);
            }
        }
    }

    // ---- epilogue ----
#pragma unroll
    for (int mi = 0; mi < 4; mi++)
#pragma unroll
        for (int nj = 0; nj < 8; nj++) {
            const float* d = acc[mi * 8 + nj];
            const int gm = bm + wm + mi * 16 + (lane >> 2);
            const int gn = bn + wn + nj * 8 + (lane & 3) * 2;
            if (gn >= N) continue;
            const float b0 = bb[gn], b1 = bb[gn + 1];
#pragma unroll
            for (int half = 0; half < 2; half++) {
                const int gr = gm + half * 8;
                if (gr >= M) continue;
                float v0 = d[half * 2 + 0] + b0;
                float v1 = d[half * 2 + 1] + b1;
                if (EPI == 1) { v0 = tanhf(v0); v1 = tanhf(v1); }
                else if (EPI == 2) { v0 = fmaxf(v0, 0.f); v1 = fmaxf(v1, 0.f); }
                if (OUT == 0) {
                    float2 o; o.x = v0; o.y = v1;
                    *reinterpret_cast<float2*>((float*)Cp + (size_t)z * cZ + (size_t)gr * ldC + gn) = o;
                } else {
                    __nv_bfloat16* Ch = (__nv_bfloat16*)Cp;
                    const size_t base = (size_t)gr * ldC + gn;
                    const __nv_bfloat16 h0 = __float2bfloat16(v0), h1 = __float2bfloat16(v1);
                    __nv_bfloat162 hp; hp.x = h0; hp.y = h1;
                    __nv_bfloat162 lp;
                    lp.x = __float2bfloat16(v0 - __bfloat162float(h0));
                    lp.y = __float2bfloat16(v1 - __bfloat162float(h1));
                    *reinterpret_cast<__nv_bfloat162*>(Ch + base) = hp;
                    *reinterpret_cast<__nv_bfloat162*>(Ch + cLo + base) = lp;
                }
            }
        }
}

// ---------------- preconvert: fp32 [rows x cols] -> padded hi/lo bf16 planes ----------------
__global__ void conv2plane(const float* __restrict__ src, __nv_bfloat16* __restrict__ dst,
                           int rows, int cols, int rowsPad, int colsPad) {
    const size_t nG = (size_t)rowsPad * (colsPad >> 3);
    const size_t g = (size_t)blockIdx.x * blockDim.x + threadIdx.x;
    if (g >= nG) return;
    const int gpr = colsPad >> 3;
    const int row = (int)(g / gpr), c8 = (int)(g % gpr) * 8;
    float v[8];
    if (row < rows && c8 + 8 <= cols) {
        const float4 a = *reinterpret_cast<const float4*>(src + (size_t)row * cols + c8);
        const float4 b = *reinterpret_cast<const float4*>(src + (size_t)row * cols + c8 + 4);
        v[0] = a.x; v[1] = a.y; v[2] = a.z; v[3] = a.w;
        v[4] = b.x; v[5] = b.y; v[6] = b.z; v[7] = b.w;
    } else {
#pragma unroll
        for (int j = 0; j < 8; j++)
            v[j] = (row < rows && c8 + j < cols) ? src[(size_t)row * cols + c8 + j] : 0.f;
    }
    uint4 hi, lo;
    __nv_bfloat16* ph = reinterpret_cast<__nv_bfloat16*>(&hi);
    __nv_bfloat16* pl = reinterpret_cast<__nv_bfloat16*>(&lo);
#pragma unroll
    for (int j = 0; j < 8; j++) {
        const __nv_bfloat16 h = __float2bfloat16(v[j]);
        ph[j] = h;
        pl[j] = __float2bfloat16(v[j] - __bfloat162float(h));
    }
    const size_t o = (size_t)row * colsPad + c8;
    *reinterpret_cast<uint4*>(dst + o) = hi;
    *reinterpret_cast<uint4*>(dst + (size_t)rowsPad * colsPad + o) = lo;
}

// ---------------- bias packing ----------------
__global__ void bias_pack(const float* b0, const float* b1, const float* b2,
                          const float* b3, const float* b4, const float* b5,
                          const float* bhg, const float* bp1, const float* bp2) {
    const int t = threadIdx.x;  // 1024 threads
    if (t < 512) {
        const float v = (t < PDIM) ? 1.f : 0.f;
        g_bias[0 * 512 + t] = (t < PDIM) ? b0[t] : 0.f;
        g_bias[1 * 512 + t] = (t < PDIM) ? b1[t] : 0.f;
        g_bias[2 * 512 + t] = (t < PDIM) ? b2[t] : 0.f;
        g_bias[3 * 512 + t] = (t < PDIM) ? b3[t] : 0.f;
        g_bias[4 * 512 + t] = (t < PDIM) ? b4[t] : 0.f;
        g_bias[5 * 512 + t] = (t < PDIM) ? b5[t] : 0.f;
        g_bias[3072 + t] = (t < ZDIM) ? bhg[t] : 0.f;
        (void)v;
    }
    g_bias[3584 + t] = (t < H1D) ? bp1[t] : 0.f;
    if (t < 256) g_bias[4608 + t] = (t < H2D) ? bp2[t] : 0.f;
}

// ---------------- fused retrieved-sum + edge-mean -> g_aM plane ----------------
__global__ void build_means_fused() {
    const int idx = blockIdx.x * blockDim.x + threadIdx.x;
    if (idx >= BSZ * (PDIM / 4)) return;
    const int b = idx / (PDIM / 4), p4 = (idx % (PDIM / 4)) * 4;

    const float4 et = *reinterpret_cast<const float4*>(g_E + ((size_t)0 * BSZ + b) * PDIM + p4);
    const float4 ev = *reinterpret_cast<const float4*>(g_E + ((size_t)1 * BSZ + b) * PDIM + p4);
    const float4 eu = *reinterpret_cast<const float4*>(g_E + ((size_t)2 * BSZ + b) * PDIM + p4);

    float4 S[3];
#pragma unroll
    for (int s = 0; s < 3; s++) {
        const float* base = g_Rout + (size_t)s * NRET * PDIM + (size_t)b * RNUM * PDIM + p4;
        float4 a = make_float4(0.f, 0.f, 0.f, 0.f);
#pragma unroll
        for (int i = 0; i < RNUM; i++) {
            const float4 v = *reinterpret_cast<const float4*>(base + (size_t)i * PDIM);
            a.x += v.x; a.y += v.y; a.z += v.z; a.w += v.w;
        }
        S[s] = a;
    }
    const float i3 = 1.f / 3.f, i11 = 1.f / 11.f;
    float o[4][4];
    o[0][0] = (et.x + ev.x + eu.x) * i3; o[0][1] = (et.y + ev.y + eu.y) * i3;
    o[0][2] = (et.z + ev.z + eu.z) * i3; o[0][3] = (et.w + ev.w + eu.w) * i3;
    o[1][0] = (S[0].x + et.x) * i11; o[1][1] = (S[0].y + et.y) * i11;
    o[1][2] = (S[0].z + et.z) * i11; o[1][3] = (S[0].w + et.w) * i11;
    o[2][0] = (S[1].x + ev.x) * i11; o[2][1] = (S[1].y + ev.y) * i11;
    o[2][2] = (S[1].z + ev.z) * i11; o[2][3] = (S[1].w + ev.w) * i11;
    o[3][0] = (S[2].x + eu.x) * i11; o[3][1] = (S[2].y + eu.y) * i11;
    o[3][2] = (S[2].z + eu.z) * i11; o[3][3] = (S[2].w + eu.w) * i11;

    const size_t loOff = (size_t)MROWS_P * KP_HG;
#pragma unroll
    for (int e = 0; e < 4; e++) {
        const size_t base = (size_t)(b * 4 + e) * KP_HG + p4;
#pragma unroll
        for (int j = 0; j < 4; j++)
            store_hl(g_aM + base + j, g_aM + loOff + base + j, o[e][j]);
    }
}

__global__ void build_pair_means() {
    const int idx = blockIdx.x * blockDim.x + threadIdx.x;
    if (idx >= RNUM * PDIM) return;
    const int i = idx / PDIM, p = idx % PDIM;
    const float a = g_Rout[(size_t)0 * NRET * PDIM + (size_t)i * PDIM + p];
    const float c = g_Rout[(size_t)1 * NRET * PDIM + (size_t)i * PDIM + p];
    const float v = 0.5f * (a + c);
    const size_t base = (size_t)(EDGE_ROWS + i) * KP_HG + p;
    store_hl(g_aM + base, g_aM + (size_t)MROWS_P * KP_HG + base, v);
}

// ---------------- feature assembly -> g_aF plane ----------------
__global__ void build_feat(const float* __restrict__ similarity,
                           const float* __restrict__ rlabel,
                           const float* __restrict__ lbl_w,
                           const float* __restrict__ lbl_b) {
    const int b = blockIdx.x;
    __shared__ float ssim[RNUM];
    __shared__ float s_lbl;
    if (threadIdx.x == 0) {
        float v[RNUM], mx = -1e30f;
#pragma unroll
        for (int i = 0; i < RNUM; i++) { v[i] = similarity[b * RNUM + i]; mx = fmaxf(mx, v[i]); }
        float sum = 0.f;
#pragma unroll
        for (int i = 0; i < RNUM; i++) { v[i] = expf(v[i] - mx); sum += v[i]; }
        float la = 0.f;
        const float inv = 1.f / sum;
#pragma unroll
        for (int i = 0; i < RNUM; i++) {
            v[i] *= inv; ssim[i] = v[i];
            la += v[i] * rlabel[b * RNUM + i];
        }
        s_lbl = la;
    }
    __syncthreads();
    const float* Yb = g_Y + (size_t)b * 4 * ZDIM;
    const float lagg = s_lbl;
    const size_t rb = (size_t)b * KP_P1;
    const size_t loOff = (size_t)BSZ * KP_P1;
    for (int z = threadIdx.x; z < ZDIM; z += blockDim.x) {
        const float Y0 = Yb[z], Y1 = Yb[ZDIM + z], Y2 = Yb[2 * ZDIM + z], Y3 = Yb[3 * ZDIM + z];
        float f[7];
        f[0] = fmaxf(0.5f * (Y0 + Y1), 0.f);
        f[1] = fmaxf(0.5f * (Y0 + Y2), 0.f);
        f[2] = fmaxf(0.5f * (Y0 + Y3), 0.f);
        float rv, rt;
        if (b != 0) {
            rv = fmaxf(Y2, 0.f);
            rt = fmaxf(Y1, 0.f);
        } else {
            rv = 0.f; rt = 0.f;
#pragma unroll
            for (int i = 0; i < RNUM; i++) {
                const float yp = g_Y[(size_t)(EDGE_ROWS + i) * ZDIM + z];
                rt += ssim[i] * fmaxf(0.5f * (Y1 + yp), 0.f);
                rv += ssim[i] * fmaxf(0.5f * (Y2 + yp), 0.f);
            }
        }
        f[3] = rv;
        f[4] = rt;
        f[5] = fmaxf(Y3, 0.f);
        f[6] = fmaxf(lagg * lbl_w[z] + lbl_b[z], 0.f);
#pragma unroll
        for (int s = 0; s < 7; s++) {
            const size_t o = rb + s * ZDIM + z;
            store_hl(g_aF + o, g_aF + loOff + o, f[s]);
        }
    }
}

__global__ void final_out(const float* __restrict__ p3_w, const float* __restrict__ p3_b,
                          float* __restrict__ out) {
    const int warp = (blockIdx.x * blockDim.x + threadIdx.x) >> 5;
    const int lane = threadIdx.x & 31;
    if (warp >= BSZ) return;
    const float* h = g_h2 + (size_t)warp * H2D;
    float s = 0.f;
    for (int j = lane; j < H2D; j += 32) s += h[j] * p3_w[j];
#pragma unroll
    for (int off = 16; off; off >>= 1) s += __shfl_xor_sync(0xffffffffu, s, off);
    if (lane == 0) out[warp] = 1.f / (1.f + expf(-(s + p3_b[0])));
}

// ---------------- host launcher ----------------
extern "C" void kernel_launch(void* const* d_in, const int* in_sizes, int n_in,
                              void* d_out, int out_size) {
    const float* vis   = (const float*)d_in[0];
    const float* txt   = (const float*)d_in[1];
    const float* sim   = (const float*)d_in[2];
    const float* rvis  = (const float*)d_in[3];
    const float* rtxt  = (const float*)d_in[4];
    const float* rlbl  = (const float*)d_in[5];
    const float* usr   = (const float*)d_in[6];
    const float* rusr  = (const float*)d_in[7];
    const float* vis_w = (const float*)d_in[9],  *vis_b = (const float*)d_in[10];
    const float* txt_w = (const float*)d_in[11], *txt_b = (const float*)d_in[12];
    const float* usr_w = (const float*)d_in[13], *usr_b = (const float*)d_in[14];
    const float* rvis_w = (const float*)d_in[15], *rvis_b = (const float*)d_in[16];
    const float* rtxt_w = (const float*)d_in[17], *rtxt_b = (const float*)d_in[18];
    const float* rusr_w = (const float*)d_in[19], *rusr_b = (const float*)d_in[20];
    const float* hg_w  = (const float*)d_in[21], *hg_b = (const float*)d_in[22];
    const float* lbl_w = (const float*)d_in[23], *lbl_b = (const float*)d_in[24];
    const float* p1_w  = (const float*)d_in[25], *p1_b = (const float*)d_in[26];
    const float* p2_w  = (const float*)d_in[27], *p2_b = (const float*)d_in[28];
    const float* p3_w  = (const float*)d_in[29], *p3_b = (const float*)d_in[30];

    float *Rout, *E, *Y, *h2, *biasD;
    __nv_bfloat16 *aS, *aR, *wE, *aM, *wHg, *aF, *wP1, *aH1, *wP2;
    cudaGetSymbolAddress((void**)&Rout, g_Rout);
    cudaGetSymbolAddress((void**)&E, g_E);
    cudaGetSymbolAddress((void**)&Y, g_Y);
    cudaGetSymbolAddress((void**)&h2, g_h2);
    cudaGetSymbolAddress((void**)&biasD, g_bias);
    cudaGetSymbolAddress((void**)&aS, g_aS);
    cudaGetSymbolAddress((void**)&aR, g_aR);
    cudaGetSymbolAddress((void**)&wE, g_wE);
    cudaGetSymbolAddress((void**)&aM, g_aM);
    cudaGetSymbolAddress((void**)&wHg, g_wHg);
    cudaGetSymbolAddress((void**)&aF, g_aF);
    cudaGetSymbolAddress((void**)&wP1, g_wP1);
    cudaGetSymbolAddress((void**)&aH1, g_aH1);
    cudaGetSymbolAddress((void**)&wP2, g_wP2);

    cudaFuncSetAttribute(hgemm<1,0>, cudaFuncAttributeMaxDynamicSharedMemorySize, SMEM_BYTES);
    cudaFuncSetAttribute(hgemm<0,0>, cudaFuncAttributeMaxDynamicSharedMemorySize, SMEM_BYTES);
    cudaFuncSetAttribute(hgemm<2,1>, cudaFuncAttributeMaxDynamicSharedMemorySize, SMEM_BYTES);
    cudaFuncSetAttribute(hgemm<2,0>, cudaFuncAttributeMaxDynamicSharedMemorySize, SMEM_BYTES);

    // ---- 0) pack biases + preconvert inputs/weights to hi/lo planes ----
    bias_pack<<<1, 1024>>>(txt_b, vis_b, usr_b, rtxt_b, rvis_b, rusr_b, hg_b, p1_b, p2_b);

    auto conv = [&](const float* src, __nv_bfloat16* dst, int rows, int cols, int rp, int cp) {
        const size_t nG = (size_t)rp * (cp >> 3);
        conv2plane<<<(unsigned)((nG + 255) / 256), 256>>>(src, dst, rows, cols, rp, cp);
    };
    const size_t aSz = 2ull * BSZ * FDIM, aRz = 2ull * NRET * FDIM, wEz = 2ull * 512 * FDIM;
    conv(txt,  aS + 0 * aSz, BSZ, FDIM, BSZ, FDIM);
    conv(vis,  aS + 1 * aSz, BSZ, FDIM, BSZ, FDIM);
    conv(usr,  aS + 2 * aSz, BSZ, FDIM, BSZ, FDIM);
    conv(rtxt, aR + 0 * aRz, NRET, FDIM, NRET, FDIM);
    conv(rvis, aR + 1 * aRz, NRET, FDIM, NRET, FDIM);
    conv(rusr, aR + 2 * aRz, NRET, FDIM, NRET, FDIM);
    conv(txt_w,  wE + 0 * wEz, PDIM, FDIM, 512, FDIM);
    conv(vis_w,  wE + 1 * wEz, PDIM, FDIM, 512, FDIM);
    conv(usr_w,  wE + 2 * wEz, PDIM, FDIM, 512, FDIM);
    conv(rtxt_w, wE + 3 * wEz, PDIM, FDIM, 512, FDIM);
    conv(rvis_w, wE + 4 * wEz, PDIM, FDIM, 512, FDIM);
    conv(rusr_w, wE + 5 * wEz, PDIM, FDIM, 512, FDIM);
    conv(hg_w, wHg, ZDIM, PDIM, 512, KP_HG);
    conv(p1_w, wP1, H1D, FEATD, 1024, KP_P1);
    conv(p2_w, wP2, H2D, H1D, 256, KP_P2);

    // ---- 1) embeddings ----
    // singles: M=4096, N=500, Kp=768, z=0..2
    hgemm<1,0><<<dim3(2, 32, 3), 256, SMEM_BYTES>>>(
        aS, aSz, (size_t)BSZ * FDIM, wE, wEz, (size_t)512 * FDIM,
        biasD, 512, E, (size_t)BSZ * PDIM, 0, PDIM, BSZ, PDIM, FDIM);
    // retrieved: M=40960
    hgemm<1,0><<<dim3(2, 320, 3), 256, SMEM_BYTES>>>(
        aR, aRz, (size_t)NRET * FDIM, wE + 3 * wEz, wEz, (size_t)512 * FDIM,
        biasD + 3 * 512, 512, Rout, (size_t)NRET * PDIM, 0, PDIM, NRET, PDIM, FDIM);

    // ---- 2) means -> g_aM plane ----
    build_means_fused<<<(BSZ * (PDIM / 4) + 255) / 256, 256>>>();
    build_pair_means<<<(RNUM * PDIM + 255) / 256, 256>>>();

    // ---- 3) hg projection: M=16394, N=300, Kp=512 -> g_Y fp32 ----
    hgemm<0,0><<<dim3(2, 129, 1), 256, SMEM_BYTES>>>(
        aM, 0, (size_t)MROWS_P * KP_HG, wHg, 0, (size_t)512 * KP_HG,
        biasD + 3072, 0, Y, 0, 0, ZDIM, M_ROWS, ZDIM, KP_HG);

    // ---- 4) feature assembly -> g_aF plane ----
    build_feat<<<BSZ, 256>>>(sim, rlbl, lbl_w, lbl_b);

    // ---- 5) MLP head ----
    // p1: M=4096, N=800, Kp=2112 -> g_aH1 plane
    hgemm<2,1><<<dim3(4, 32, 1), 256, SMEM_BYTES>>>(
        aF, 0, (size_t)BSZ * KP_P1, wP1, 0, (size_t)1024 * KP_P1,
        biasD + 3584, 0, aH1, 0, (size_t)BSZ * KP_P2, KP_P2, BSZ, H1D, KP_P1);
    // p2: M=4096, N=200, Kp=800 -> g_h2 fp32
    hgemm<2,0><<<dim3(1, 32, 1), 256, SMEM_BYTES>>>(
        aH1, 0, (size_t)BSZ * KP_P2, wP2, 0, (size_t)256 * KP_P2,
        biasD + 4608, 0, h2, 0, 0, H2D, BSZ, H2D, KP_P2);

    final_out<<<(BSZ * 32 + 255) / 256, 256>>>(p3_w, p3_b, (float*)d_out);
}